// round 15
// baseline (speedup 1.0000x reference)
#include <cuda_runtime.h>
#include <cuda_bf16.h>
#include <cstdint>

// Problem constants
#define B_   2
#define N_   2048
#define D_   1024
#define H_   16
#define DH_  64
#define ROWS_ (B_ * N_)          // 4096 tokens
#define QKVW_ (3 * D_)           // 3072

// Scratch (static device memory; no allocation at runtime)
__device__ float g_qkv[(size_t)ROWS_ * QKVW_];   // 48 MB: q|k|v per token row
__device__ float g_ao [(size_t)ROWS_ * D_];      // 16 MB: attention output

// ---------------------------------------------------------------------------
// tf32 helpers
// ---------------------------------------------------------------------------
__device__ __forceinline__ uint32_t f32_to_tf32(float x) {
    uint32_t r;
    asm("cvt.rna.tf32.f32 %0, %1;" : "=r"(r) : "f"(x));
    return r;
}

__device__ __forceinline__ void mma_tf32_16x8x8(float* d,
                                                const uint32_t* a,
                                                const uint32_t* b) {
    asm volatile(
        "mma.sync.aligned.m16n8k8.row.col.f32.tf32.tf32.f32 "
        "{%0,%1,%2,%3}, {%4,%5,%6,%7}, {%8,%9}, {%0,%1,%2,%3};\n"
        : "+f"(d[0]), "+f"(d[1]), "+f"(d[2]), "+f"(d[3])
        : "r"(a[0]), "r"(a[1]), "r"(a[2]), "r"(a[3]),
          "r"(b[0]), "r"(b[1]));
}

// Column permutation: pairs (c, c+4) within each 8-group become adjacent,
// enabling LDS.64 for mma k-fragments. pos = (c&~7) | (2*(c&3) + ((c>>2)&1))
__device__ __forceinline__ int kperm(int c) {
    return (c & ~7) | ((2 * (c & 3)) | ((c >> 2) & 1));
}

// ---------------------------------------------------------------------------
// Kernel 1/4: tf32 tensor-core GEMM + bias (validated R5/R12).
// ---------------------------------------------------------------------------
#define AS_STRIDE 20
#define BS_STRIDE 136

__global__ __launch_bounds__(256, 2)
void gemm_tf32_bias_kernel(const float* __restrict__ A, const float* __restrict__ B,
                           const float* __restrict__ bias, float* __restrict__ C,
                           int M, int N, int K)
{
    __shared__ uint32_t As[128 * AS_STRIDE];
    __shared__ uint32_t Bs[16 * BS_STRIDE];

    const int tid  = threadIdx.x;
    const int lane = tid & 31;
    const int w    = tid >> 5;
    const int wm   = w & 3;
    const int wn   = w >> 2;
    const int g    = lane >> 2;
    const int t    = lane & 3;

    const int row0 = blockIdx.y * 128;
    const int col0 = blockIdx.x * 128;

    const int ar = tid >> 2;
    const int ac = (tid & 3) * 4;
    const int br = tid >> 5;
    const int bc = (tid & 31) * 4;

    const float* Ap0 = A + (size_t)(row0 + ar) * K + ac;
    const float* Ap1 = A + (size_t)(row0 + ar + 64) * K + ac;
    const float* Bp0 = B + (size_t)br * N + col0 + bc;
    const float* Bp1 = B + (size_t)(br + 8) * N + col0 + bc;

    float acc[2][8][4];
#pragma unroll
    for (int mt = 0; mt < 2; mt++)
#pragma unroll
        for (int nt = 0; nt < 8; nt++)
#pragma unroll
            for (int i = 0; i < 4; i++) acc[mt][nt][i] = 0.f;

    for (int k0 = 0; k0 < K; k0 += 16) {
        float4 a0 = *(const float4*)(Ap0 + k0);
        float4 a1 = *(const float4*)(Ap1 + k0);
        float4 b0 = *(const float4*)(Bp0 + (size_t)k0 * N);
        float4 b1 = *(const float4*)(Bp1 + (size_t)k0 * N);
        __syncthreads();
        uint32_t* asr0 = &As[ar * AS_STRIDE + ac];
        asr0[0] = f32_to_tf32(a0.x); asr0[1] = f32_to_tf32(a0.y);
        asr0[2] = f32_to_tf32(a0.z); asr0[3] = f32_to_tf32(a0.w);
        uint32_t* asr1 = &As[(ar + 64) * AS_STRIDE + ac];
        asr1[0] = f32_to_tf32(a1.x); asr1[1] = f32_to_tf32(a1.y);
        asr1[2] = f32_to_tf32(a1.z); asr1[3] = f32_to_tf32(a1.w);
        uint32_t* bsr0 = &Bs[br * BS_STRIDE + bc];
        bsr0[0] = f32_to_tf32(b0.x); bsr0[1] = f32_to_tf32(b0.y);
        bsr0[2] = f32_to_tf32(b0.z); bsr0[3] = f32_to_tf32(b0.w);
        uint32_t* bsr1 = &Bs[(br + 8) * BS_STRIDE + bc];
        bsr1[0] = f32_to_tf32(b1.x); bsr1[1] = f32_to_tf32(b1.y);
        bsr1[2] = f32_to_tf32(b1.z); bsr1[3] = f32_to_tf32(b1.w);
        __syncthreads();

#pragma unroll
        for (int ks = 0; ks < 16; ks += 8) {
            uint32_t afr[2][4];
#pragma unroll
            for (int mt = 0; mt < 2; mt++) {
                int r = wm * 32 + mt * 16 + g;
                afr[mt][0] = As[r * AS_STRIDE + ks + t];
                afr[mt][1] = As[(r + 8) * AS_STRIDE + ks + t];
                afr[mt][2] = As[r * AS_STRIDE + ks + t + 4];
                afr[mt][3] = As[(r + 8) * AS_STRIDE + ks + t + 4];
            }
            uint32_t bfr[8][2];
#pragma unroll
            for (int nt = 0; nt < 8; nt++) {
                int n = wn * 64 + nt * 8 + g;
                bfr[nt][0] = Bs[(ks + t) * BS_STRIDE + n];
                bfr[nt][1] = Bs[(ks + t + 4) * BS_STRIDE + n];
            }
#pragma unroll
            for (int mt = 0; mt < 2; mt++)
#pragma unroll
                for (int nt = 0; nt < 8; nt++)
                    mma_tf32_16x8x8(acc[mt][nt], afr[mt], bfr[nt]);
        }
    }

#pragma unroll
    for (int mt = 0; mt < 2; mt++) {
        int r0 = row0 + wm * 32 + mt * 16 + g;
#pragma unroll
        for (int nt = 0; nt < 8; nt++) {
            int c = col0 + wn * 64 + nt * 8 + 2 * t;
            float bv0 = bias[c], bv1 = bias[c + 1];
            float2 v0 = make_float2(acc[mt][nt][0] + bv0, acc[mt][nt][1] + bv1);
            float2 v1 = make_float2(acc[mt][nt][2] + bv0, acc[mt][nt][3] + bv1);
            *(float2*)(C + (size_t)r0 * N + c)       = v0;
            *(float2*)(C + (size_t)(r0 + 8) * N + c) = v1;
        }
    }
}

// ---------------------------------------------------------------------------
// Kernel 2/4: RMSNorm + RoPE (unchanged, validated).
// ---------------------------------------------------------------------------
__global__ __launch_bounds__(256)
void norm_rope_kernel(float* __restrict__ qkv,
                      const float* __restrict__ cosb, const float* __restrict__ sinb,
                      const float* __restrict__ q_scale, const float* __restrict__ k_scale)
{
    int row = blockIdx.x;
    int n = row & (N_ - 1);
    float* q = qkv + (size_t)row * QKVW_;
    float* k = q + D_;
    int tid = threadIdx.x;

    float sq = 0.f, sk = 0.f;
    for (int i = tid; i < D_; i += 256) {
        float a = q[i]; sq += a * a;
        float b = k[i]; sk += b * b;
    }
#pragma unroll
    for (int o = 16; o; o >>= 1) {
        sq += __shfl_xor_sync(0xffffffffu, sq, o);
        sk += __shfl_xor_sync(0xffffffffu, sk, o);
    }
    __shared__ float rq_s[8], rk_s[8];
    int w = tid >> 5, lane = tid & 31;
    if (lane == 0) { rq_s[w] = sq; rk_s[w] = sk; }
    __syncthreads();
    if (tid == 0) {
        float a = 0.f, b = 0.f;
#pragma unroll
        for (int i = 0; i < 8; i++) { a += rq_s[i]; b += rk_s[i]; }
        rq_s[0] = rsqrtf(a * (1.f / D_) + 1e-6f);
        rk_s[0] = rsqrtf(b * (1.f / D_) + 1e-6f);
    }
    __syncthreads();
    float rq = rq_s[0], rk = rk_s[0];

    for (int p = tid; p < 512; p += 256) {
        int hh = p >> 5, m = p & 31;
        int i0 = hh * 64 + 2 * m;
        float c = cosb[n * 32 + m];
        float s = sinb[n * 32 + m];
        float q0 = q[i0] * rq * q_scale[i0];
        float q1 = q[i0 + 1] * rq * q_scale[i0 + 1];
        q[i0]     = q0 * c - q1 * s;
        q[i0 + 1] = q0 * s + q1 * c;
        float k0 = k[i0] * rk * k_scale[i0];
        float k1 = k[i0 + 1] * rk * k_scale[i0 + 1];
        k[i0]     = k0 * c - k1 * s;
        k[i0 + 1] = k0 * s + k1 * c;
    }
}

// ---------------------------------------------------------------------------
// Kernel 3/4: tensor-core flash attention v2.
//   - K/Q stored with permuted columns (stride 72 floats = 36 uint2):
//     mma k-frag pair (k, k+4) = one LDS.64; 2*36 ≡ 8 mod 32 -> banks 8g+2t
//     distinct over a half-warp: conflict-free.
//   - V stored pair-packed: Vs2[(kk*4+t)*68 + n] (uint2) holds
//     (V[kk*8+t][n], V[kk*8+t+4][n]); 2*68 ≡ 8 mod 32 -> conflict-free LDS.64.
//   - Pw unchanged (stride 68, scalar, conflict-free).
//   - occupancy 4 (smem 53 248 B/block).
// ---------------------------------------------------------------------------
#define KS_F   72                      // Ks stride in floats (36 uint2)
#define VS_U2  68                      // Vs2 stride in uint2
#define PW_STRIDE 68
#define KS_WORDS (64 * KS_F)           // 4608
#define VS_WORDS (32 * VS_U2 * 2)      // 4352
#define PW_WORDS (4 * 16 * PW_STRIDE)  // 4352
#define ATTN_TC_SMEM ((KS_WORDS + VS_WORDS + PW_WORDS) * 4)   // 53248 B

__global__ __launch_bounds__(128, 4)
void attn_tc_kernel(const float* __restrict__ qkv, float* __restrict__ out)
{
    extern __shared__ uint32_t smu[];
    uint32_t* Ks  = smu;                    // [64][KS_F] permuted columns
    uint32_t* Vs2 = Ks + KS_WORDS;          // [32][VS_U2] uint2 pairs
    uint32_t* Pw  = Vs2 + VS_WORDS;         // [4][16][PW_STRIDE]

    const int tid  = threadIdx.x;
    const int lane = tid & 31;
    const int w    = tid >> 5;     // warp 0..3 -> rows w*16..w*16+15
    const int g    = lane >> 2;    // 0..7
    const int t    = lane & 3;     // 0..3

    const int q0 = blockIdx.x * 64;
    const int h  = blockIdx.y;
    const int b  = blockIdx.z;

    const float* qg = qkv + (size_t)(b * N_ + q0) * QKVW_ + h * DH_;
    const float* kg = qkv + (size_t)(b * N_) * QKVW_ + D_ + h * DH_;
    const float* vg = kg + D_;

    const uint2* Ks2 = (const uint2*)Ks;   // stride 36 per row
    const uint2* Vp2 = (const uint2*)Vs2;  // stride VS_U2 per packed row

    // ---- Stage Q (pre-scaled by 0.125, exact) into Ks with permuted columns
    {
        int r = tid >> 1, c0 = (tid & 1) * 32;
        const float* src = qg + (size_t)r * QKVW_ + c0;
        uint32_t* dst = Ks + r * KS_F;
#pragma unroll
        for (int i = 0; i < 32; i += 4) {
            float4 v = *(const float4*)(src + i);
            float vv[4] = {v.x, v.y, v.z, v.w};
#pragma unroll
            for (int j = 0; j < 4; j++) {
                int c = c0 + i + j;
                dst[kperm(c)] = f32_to_tf32(vv[j] * 0.125f);
            }
        }
    }
    __syncthreads();
    uint32_t qf[8][4];
    {
        int r = w * 16 + g;
#pragma unroll
        for (int kk = 0; kk < 8; kk++) {
            uint2 p0 = Ks2[r * 36 + kk * 4 + t];         // (k, k+4) row r
            uint2 p1 = Ks2[(r + 8) * 36 + kk * 4 + t];   // (k, k+4) row r+8
            qf[kk][0] = p0.x; qf[kk][2] = p0.y;
            qf[kk][1] = p1.x; qf[kk][3] = p1.y;
        }
    }

    float oacc[8][4];
#pragma unroll
    for (int nt = 0; nt < 8; nt++)
#pragma unroll
        for (int i = 0; i < 4; i++) oacc[nt][i] = 0.f;
    float m0 = -1e30f, m1 = -1e30f, l0 = 0.f, l1 = 0.f;

    uint32_t* pwme = Pw + w * 16 * PW_STRIDE;

    for (int kc = 0; kc < N_ / 64; kc++) {
        __syncthreads();   // previous iter's consumers done before overwrite
        // ---- Load K (permuted cols) and V (pair-packed), cvt to tf32
        {
            int r = tid >> 1, c0 = (tid & 1) * 32;
            const float* ksrc = kg + (size_t)(kc * 64 + r) * QKVW_ + c0;
            const float* vsrc = vg + (size_t)(kc * 64 + r) * QKVW_ + c0;
            uint32_t* kd = Ks + r * KS_F;
            // V row r -> packed row kk*4+p, half hi
            int kkr = r >> 3, ttr = r & 7;
            uint32_t* vd = Vs2 + ((kkr * 4 + (ttr & 3)) * VS_U2) * 2 + (ttr >> 2);
#pragma unroll
            for (int i = 0; i < 32; i += 4) {
                float4 kv = *(const float4*)(ksrc + i);
                float kvv[4] = {kv.x, kv.y, kv.z, kv.w};
                float4 vv = *(const float4*)(vsrc + i);
                float vvv[4] = {vv.x, vv.y, vv.z, vv.w};
#pragma unroll
                for (int j = 0; j < 4; j++) {
                    int c = c0 + i + j;
                    kd[kperm(c)] = f32_to_tf32(kvv[j]);
                    vd[2 * c]    = f32_to_tf32(vvv[j]);
                }
            }
        }
        __syncthreads();

        // ---- S = Q K^T (scaled): 8 n-tiles x 8 k-steps, B-frag via LDS.64
        float s[8][4];
#pragma unroll
        for (int nt = 0; nt < 8; nt++) {
            s[nt][0] = 0.f; s[nt][1] = 0.f; s[nt][2] = 0.f; s[nt][3] = 0.f;
        }
#pragma unroll
        for (int kk = 0; kk < 8; kk++) {
#pragma unroll
            for (int nt = 0; nt < 8; nt++) {
                uint2 bb = Ks2[(nt * 8 + g) * 36 + kk * 4 + t];
                uint32_t bf[2] = {bb.x, bb.y};
                mma_tf32_16x8x8(s[nt], qf[kk], bf);
            }
        }

        // ---- Online softmax in fragment registers (rows g and g+8)
        float tm0 = -1e30f, tm1 = -1e30f;
#pragma unroll
        for (int nt = 0; nt < 8; nt++) {
            tm0 = fmaxf(tm0, fmaxf(s[nt][0], s[nt][1]));
            tm1 = fmaxf(tm1, fmaxf(s[nt][2], s[nt][3]));
        }
        tm0 = fmaxf(tm0, __shfl_xor_sync(0xffffffffu, tm0, 1));
        tm0 = fmaxf(tm0, __shfl_xor_sync(0xffffffffu, tm0, 2));
        tm1 = fmaxf(tm1, __shfl_xor_sync(0xffffffffu, tm1, 1));
        tm1 = fmaxf(tm1, __shfl_xor_sync(0xffffffffu, tm1, 2));
        float mn0 = fmaxf(m0, tm0), mn1 = fmaxf(m1, tm1);
        float al0 = __expf(m0 - mn0), al1 = __expf(m1 - mn1);
        m0 = mn0; m1 = mn1;

        float sum0 = 0.f, sum1 = 0.f;
#pragma unroll
        for (int nt = 0; nt < 8; nt++) {
            s[nt][0] = __expf(s[nt][0] - mn0);
            s[nt][1] = __expf(s[nt][1] - mn0);
            s[nt][2] = __expf(s[nt][2] - mn1);
            s[nt][3] = __expf(s[nt][3] - mn1);
            sum0 += s[nt][0] + s[nt][1];
            sum1 += s[nt][2] + s[nt][3];
        }
        sum0 += __shfl_xor_sync(0xffffffffu, sum0, 1);
        sum0 += __shfl_xor_sync(0xffffffffu, sum0, 2);
        sum1 += __shfl_xor_sync(0xffffffffu, sum1, 1);
        sum1 += __shfl_xor_sync(0xffffffffu, sum1, 2);
        l0 = l0 * al0 + sum0;
        l1 = l1 * al1 + sum1;

        // ---- Rescale O accumulator
#pragma unroll
        for (int nt = 0; nt < 8; nt++) {
            oacc[nt][0] *= al0; oacc[nt][1] *= al0;
            oacc[nt][2] *= al1; oacc[nt][3] *= al1;
        }

        // ---- Write P (tf32) to warp-private smem (unpermuted)
#pragma unroll
        for (int nt = 0; nt < 8; nt++) {
            uint2 v0, v1;
            v0.x = f32_to_tf32(s[nt][0]); v0.y = f32_to_tf32(s[nt][1]);
            v1.x = f32_to_tf32(s[nt][2]); v1.y = f32_to_tf32(s[nt][3]);
            *(uint2*)&pwme[g * PW_STRIDE + nt * 8 + 2 * t]       = v0;
            *(uint2*)&pwme[(g + 8) * PW_STRIDE + nt * 8 + 2 * t] = v1;
        }
        __syncwarp();

        // ---- O += P @ V : B-frag via LDS.64 from pair-packed V
#pragma unroll
        for (int kk = 0; kk < 8; kk++) {
            uint32_t af[4];
            af[0] = pwme[g * PW_STRIDE + kk * 8 + t];
            af[1] = pwme[(g + 8) * PW_STRIDE + kk * 8 + t];
            af[2] = pwme[g * PW_STRIDE + kk * 8 + t + 4];
            af[3] = pwme[(g + 8) * PW_STRIDE + kk * 8 + t + 4];
#pragma unroll
            for (int nt = 0; nt < 8; nt++) {
                uint2 bb = Vp2[(kk * 4 + t) * VS_U2 + nt * 8 + g];
                uint32_t bf[2] = {bb.x, bb.y};
                mma_tf32_16x8x8(oacc[nt], af, bf);
            }
        }
        __syncwarp();   // Pw stable before next iteration's overwrite
    }

    // ---- Finalize: divide by l, store
    float inv0 = 1.f / l0, inv1 = 1.f / l1;
    float* og = out + (size_t)(b * N_ + q0 + w * 16) * D_ + h * DH_;
#pragma unroll
    for (int nt = 0; nt < 8; nt++) {
        float2 r0 = make_float2(oacc[nt][0] * inv0, oacc[nt][1] * inv0);
        float2 r1 = make_float2(oacc[nt][2] * inv1, oacc[nt][3] * inv1);
        *(float2*)(og + (size_t)g * D_ + nt * 8 + 2 * t)       = r0;
        *(float2*)(og + (size_t)(g + 8) * D_ + nt * 8 + 2 * t) = r1;
    }
}

// ---------------------------------------------------------------------------
extern "C" void kernel_launch(void* const* d_in, const int* in_sizes, int n_in,
                              void* d_out, int out_size)
{
    const float* x       = (const float*)d_in[0];   // [2,2048,1024]
    const float* cosb    = (const float*)d_in[1];   // [2048,32]
    const float* sinb    = (const float*)d_in[2];   // [2048,32]
    const float* Wqkv    = (const float*)d_in[3];   // [1024,3072]
    const float* bqkv    = (const float*)d_in[4];   // [3072]
    const float* q_scale = (const float*)d_in[5];   // [1024]
    const float* k_scale = (const float*)d_in[6];   // [1024]
    const float* Wout    = (const float*)d_in[7];   // [1024,1024]
    const float* bout    = (const float*)d_in[8];   // [1024]
    float* out = (float*)d_out;                     // [2,2048,1024]

    float* qkv_p = nullptr;
    float* ao_p  = nullptr;
    cudaGetSymbolAddress((void**)&qkv_p, g_qkv);
    cudaGetSymbolAddress((void**)&ao_p, g_ao);
    cudaFuncSetAttribute(attn_tc_kernel, cudaFuncAttributeMaxDynamicSharedMemorySize,
                         ATTN_TC_SMEM);

    // 1) qkv = x @ Wqkv + bqkv   (tf32 tensor cores)
    {
        dim3 grid(QKVW_ / 128, ROWS_ / 128);
        gemm_tf32_bias_kernel<<<grid, 256>>>(x, Wqkv, bqkv, qkv_p, ROWS_, QKVW_, D_);
    }
    // 2) rmsnorm + rope on q,k (in place)
    norm_rope_kernel<<<ROWS_, 256>>>(qkv_p, cosb, sinb, q_scale, k_scale);

    // 3) attention (tf32 tensor cores, flash, LDS.64 fragment paths)
    {
        dim3 grid(N_ / 64, H_, B_);
        attn_tc_kernel<<<grid, 128, ATTN_TC_SMEM>>>(qkv_p, ao_p);
    }
    // 4) out = ao @ Wout + bout   (tf32 tensor cores)
    {
        dim3 grid(D_ / 128, ROWS_ / 128);
        gemm_tf32_bias_kernel<<<grid, 256>>>(ao_p, Wout, bout, out, ROWS_, D_, D_);
    }
}